// round 13
// baseline (speedup 1.0000x reference)
#include <cuda_runtime.h>
#include <cuda_fp16.h>
#include <stdint.h>

#define Nn   20000
#define Ee   320000
#define Hh   128
#define Ll   3
#define IND  6
#define PED  8
#define OUTD 4

// ---------------- scratch (static device globals; no allocation) -------------
__device__ float g_h_nodes[(size_t)Nn * Hh];
__device__ float g_h_edges[(size_t)Ee * Hh];
__device__ float g_m_node[(size_t)Nn * Hh];
// pre-split fp16 weight chunks: each chunk = [plane(hi,lo)][16 k][128 n] = 4096 halfs.
// 0..7: ee_W2 ; 8+32l..: eu_W1(24), eu_W2(8) ; 104+40l..: nu_W1(16), nu_W2(8), fu_W1(8), fu_W2(8)
__device__ unsigned short g_wc[224 * 4096];

// ---------------- SMEM layouts (bytes) ---------------------------------------
// 64-row kernels (node_update, edge_encode)
#define EU_AS  512
#define EU_BS  12800
#define EU_HSM 30208
#define EU_SMEM 65024
#define EE_W1  0
#define EE_B1  2048
#define EE_HSM 2560
#define EE_BS  37376
#define EE_SMEM 54784
#define AS_DB 6144
#define AS_PL 3072
#define AS_ROW 48
#define BS_DB 8704
#define BS_PL 4352
#define BS_ROW 272
#define HSM_PL 17408
#define HSM_ROW 272
// 128-row edge_update kernel
#define E2_SRC 0
#define E2_DST 512
#define E2_AS  1024
#define AS2_PL 6144
#define AS2_DB 12288
#define E2_BS  25600
#define E2_HSM 43008
#define HSM2_PL 34816
#define E2_SMEM 112640

// ---------------- asm wrappers -----------------------------------------------
__device__ __forceinline__ uint32_t smem_u32(const void* p) {
    uint32_t a;
    asm("{ .reg .u64 t; cvta.to.shared.u64 t, %1; cvt.u32.u64 %0, t; }" : "=r"(a) : "l"(p));
    return a;
}
__device__ __forceinline__ void ldsm_x4(uint32_t* r, uint32_t a) {
    asm volatile("ldmatrix.sync.aligned.m8n8.x4.shared.b16 {%0,%1,%2,%3}, [%4];"
                 : "=r"(r[0]), "=r"(r[1]), "=r"(r[2]), "=r"(r[3]) : "r"(a));
}
__device__ __forceinline__ void ldsm_x4t(uint32_t* r, uint32_t a) {
    asm volatile("ldmatrix.sync.aligned.m8n8.x4.trans.shared.b16 {%0,%1,%2,%3}, [%4];"
                 : "=r"(r[0]), "=r"(r[1]), "=r"(r[2]), "=r"(r[3]) : "r"(a));
}
__device__ __forceinline__ void mma16816(float* c, const uint32_t* a, const uint32_t* b) {
    asm volatile("mma.sync.aligned.m16n8k16.row.col.f32.f16.f16.f32 "
                 "{%0,%1,%2,%3}, {%4,%5,%6,%7}, {%8,%9}, {%0,%1,%2,%3};"
                 : "+f"(c[0]), "+f"(c[1]), "+f"(c[2]), "+f"(c[3])
                 : "r"(a[0]), "r"(a[1]), "r"(a[2]), "r"(a[3]), "r"(b[0]), "r"(b[1]));
}
__device__ __forceinline__ uint32_t packh2(__half a, __half b) {
    __half2 h = __halves2half2(a, b);
    return *reinterpret_cast<uint32_t*>(&h);
}
__device__ __forceinline__ void split2h(float x, float y, uint32_t& hi, uint32_t& lo) {
    __half hx = __float2half_rn(x), hy = __float2half_rn(y);
    lo = packh2(__float2half_rn(x - __half2float(hx)),
                __float2half_rn(y - __half2float(hy)));
    hi = packh2(hx, hy);
}
__device__ __forceinline__ void zero_acc8(float acc[2][4][4]) {
#pragma unroll
    for (int i = 0; i < 2; i++)
#pragma unroll
        for (int j = 0; j < 4; j++)
#pragma unroll
            for (int k = 0; k < 4; k++) acc[i][j][k] = 0.f;
}
__device__ __forceinline__ void zero_acc16(float acc[2][8][4]) {
#pragma unroll
    for (int i = 0; i < 2; i++)
#pragma unroll
        for (int j = 0; j < 8; j++)
#pragma unroll
            for (int k = 0; k < 4; k++) acc[i][j][k] = 0.f;
}

// ---- 64-row chunk: 3-term split mma over warp tile 32x32 --------------------
__device__ __forceinline__ void mma_chunk(uint32_t aHi, uint32_t aLo, uint32_t mfs,
                                          uint32_t bHi, uint32_t bLo,
                                          float acc[2][4][4]) {
    uint32_t ah[2][4], al[2][4], bh[8], bl[8];
    ldsm_x4(ah[0], aHi);
    ldsm_x4(ah[1], aHi + mfs);
    ldsm_x4(al[0], aLo);
    ldsm_x4(al[1], aLo + mfs);
    ldsm_x4t(bh, bHi);
    ldsm_x4t(bh + 4, bHi + 32);
    ldsm_x4t(bl, bLo);
    ldsm_x4t(bl + 4, bLo + 32);
#pragma unroll
    for (int mf = 0; mf < 2; mf++)
#pragma unroll
        for (int nf = 0; nf < 4; nf++) {
            mma16816(acc[mf][nf], ah[mf], bh + 2 * nf);
            mma16816(acc[mf][nf], ah[mf], bl + 2 * nf);
            mma16816(acc[mf][nf], al[mf], bh + 2 * nf);
        }
}

// ---- 128-row chunk: warp tile 32x64 -----------------------------------------
__device__ __forceinline__ void mma_chunk128(uint32_t aHi, uint32_t aLo, uint32_t mfs,
                                             uint32_t bHi, uint32_t bLo,
                                             float acc[2][8][4]) {
    uint32_t ah[2][4], al[2][4], bh[16], bl[16];
    ldsm_x4(ah[0], aHi);
    ldsm_x4(ah[1], aHi + mfs);
    ldsm_x4(al[0], aLo);
    ldsm_x4(al[1], aLo + mfs);
    ldsm_x4t(bh, bHi);
    ldsm_x4t(bh + 4, bHi + 32);
    ldsm_x4t(bh + 8, bHi + 64);
    ldsm_x4t(bh + 12, bHi + 96);
    ldsm_x4t(bl, bLo);
    ldsm_x4t(bl + 4, bLo + 32);
    ldsm_x4t(bl + 8, bLo + 64);
    ldsm_x4t(bl + 12, bLo + 96);
#pragma unroll
    for (int mf = 0; mf < 2; mf++)
#pragma unroll
        for (int nf = 0; nf < 8; nf++) {
            mma16816(acc[mf][nf], ah[mf], bh + 2 * nf);
            mma16816(acc[mf][nf], ah[mf], bl + 2 * nf);
            mma16816(acc[mf][nf], al[mf], bh + 2 * nf);
        }
}

// 64-row stage GEMM: A = Hsm (64x128 split fp16), B = 8 streamed weight chunks
__device__ __forceinline__ void run_stage2(char* sm, uint32_t smb,
                                           uint32_t HsmOff, uint32_t BsOff,
                                           const unsigned short* wsrc,
                                           float acc[2][4][4],
                                           int tid, int lane, int warpM, int warpN) {
    const int bpl = tid >> 7, brow = (tid >> 3) & 15, bseg = tid & 7;
    const unsigned short* g0 = wsrc + bpl * 2048 + brow * 128 + bseg * 8;
    char* bdst0 = sm + BsOff + bpl * BS_PL + brow * BS_ROW + bseg * 16;
    {
        uint4 v0 = *(const uint4*)g0;
        uint4 v1 = *(const uint4*)(g0 + 64);
        *(uint4*)bdst0 = v0;
        *(uint4*)(bdst0 + 128) = v1;
    }
    __syncthreads();
    const uint32_t aB = smb + HsmOff + (warpM * 32 + (lane & 15)) * HSM_ROW + (lane >> 4) * 16;
    const uint32_t bB = smb + BsOff + (((lane >> 3) & 1) * 8 + (lane & 7)) * BS_ROW
                        + (warpN * 32 + (lane >> 4) * 8) * 2;
    for (int c = 0; c < 8; c++) {
        const int db = c & 1;
        uint4 w0, w1;
        if (c < 7) {
            const unsigned short* g2 = g0 + (size_t)(c + 1) * 4096;
            w0 = *(const uint4*)g2;
            w1 = *(const uint4*)(g2 + 64);
        }
        mma_chunk(aB + c * 32, aB + c * 32 + HSM_PL, 16 * HSM_ROW,
                  bB + db * BS_DB, bB + db * BS_DB + BS_PL, acc);
        if (c < 7) {
            char* d = bdst0 + (db ^ 1) * BS_DB;
            *(uint4*)d = w0;
            *(uint4*)(d + 128) = w1;
        }
        __syncthreads();
    }
}

// 128-row stage GEMM over E2_HSM
__device__ __forceinline__ void run_stage2_128(char* sm, uint32_t smb,
                                               const unsigned short* wsrc,
                                               float acc[2][8][4],
                                               int tid, int lane, int warpM, int warpN) {
    const int bpl = tid >> 7, brow = (tid >> 3) & 15, bseg = tid & 7;
    const unsigned short* g0 = wsrc + bpl * 2048 + brow * 128 + bseg * 8;
    char* bdst0 = sm + E2_BS + bpl * BS_PL + brow * BS_ROW + bseg * 16;
    {
        uint4 v0 = *(const uint4*)g0;
        uint4 v1 = *(const uint4*)(g0 + 64);
        *(uint4*)bdst0 = v0;
        *(uint4*)(bdst0 + 128) = v1;
    }
    __syncthreads();
    const uint32_t aB = smb + E2_HSM + (warpM * 32 + (lane & 15)) * HSM_ROW + (lane >> 4) * 16;
    const uint32_t bB = smb + E2_BS + (((lane >> 3) & 1) * 8 + (lane & 7)) * BS_ROW
                        + (warpN * 64 + (lane >> 4) * 8) * 2;
    for (int c = 0; c < 8; c++) {
        const int db = c & 1;
        uint4 w0, w1;
        if (c < 7) {
            const unsigned short* g2 = g0 + (size_t)(c + 1) * 4096;
            w0 = *(const uint4*)g2;
            w1 = *(const uint4*)(g2 + 64);
        }
        mma_chunk128(aB + c * 32, aB + c * 32 + HSM2_PL, 16 * HSM_ROW,
                     bB + db * BS_DB, bB + db * BS_DB + BS_PL, acc);
        if (c < 7) {
            char* d = bdst0 + (db ^ 1) * BS_DB;
            *(uint4*)d = w0;
            *(uint4*)(d + 128) = w1;
        }
        __syncthreads();
    }
}

// ---------------- weight prep: split fp16 chunks into g_wc -------------------
__global__ void prep_weights(const float* __restrict__ ee_W2,
                             const float* __restrict__ eu_W1,
                             const float* __restrict__ eu_W2,
                             const float* __restrict__ nu_W1,
                             const float* __restrict__ nu_W2,
                             const float* __restrict__ fu_W1,
                             const float* __restrict__ fu_W2) {
    const int cid = blockIdx.x;  // 0..223
    const float* W;
    int koff;
    if (cid < 8) { W = ee_W2; koff = cid * 16; }
    else if (cid < 104) {
        int rel = cid - 8, l = rel / 32, c = rel % 32;
        if (c < 24) { W = eu_W1 + (size_t)l * 3 * Hh * Hh; koff = c * 16; }
        else        { W = eu_W2 + (size_t)l * Hh * Hh;     koff = (c - 24) * 16; }
    } else {
        int rel = cid - 104, l = rel / 40, c = rel % 40;
        if (c < 16)      { W = nu_W1 + (size_t)l * 2 * Hh * Hh; koff = c * 16; }
        else if (c < 24) { W = nu_W2 + (size_t)l * Hh * Hh;     koff = (c - 16) * 16; }
        else if (c < 32) { W = fu_W1 + (size_t)l * Hh * Hh;     koff = (c - 24) * 16; }
        else             { W = fu_W2 + (size_t)l * Hh * Hh;     koff = (c - 32) * 16; }
    }
    unsigned short* out = g_wc + (size_t)cid * 4096;
    for (int idx = threadIdx.x; idx < 2048; idx += blockDim.x) {
        int k = idx >> 7, n = idx & 127;
        float v = W[(size_t)(koff + k) * 128 + n];
        __half h = __float2half_rn(v);
        __half lo = __float2half_rn(v - __half2float(h));
        out[idx] = *reinterpret_cast<unsigned short*>(&h);
        out[2048 + idx] = *reinterpret_cast<unsigned short*>(&lo);
    }
}

// ---------------- edge update: 128-row HMMA tile + fused scatter-add ---------
__global__ __launch_bounds__(256)
void edge_update_mma(const float* __restrict__ hn, float* __restrict__ he,
                     const int* __restrict__ src, const int* __restrict__ dst,
                     const unsigned short* __restrict__ w1c,
                     const unsigned short* __restrict__ w2c,
                     const float* __restrict__ b1, const float* __restrict__ b2,
                     float* __restrict__ mnode) {
    extern __shared__ char sm[];
    const uint32_t smb = smem_u32(sm);
    const int tid = threadIdx.x, lane = tid & 31, wid = tid >> 5;
    const int warpM = wid & 3, warpN = wid >> 2;
    const int row_base = blockIdx.x * 128;
    int* s_src = (int*)(sm + E2_SRC);
    int* s_dst = (int*)(sm + E2_DST);
    if (tid < 128) s_src[tid] = src[row_base + tid];
    else s_dst[tid - 128] = dst[row_base + tid - 128];
    __syncthreads();

    float acc[2][8][4];
    zero_acc16(acc);

    // -------- stage 1: hidden = relu([h_src||h_dst||h_edge] @ W1 + b1) -------
    const int ga_row = tid >> 1, ga_half = tid & 1;
    const int bpl = tid >> 7, brow = (tid >> 3) & 15, bseg = tid & 7;
    const unsigned short* gB0 = w1c + bpl * 2048 + brow * 128 + bseg * 8;
    char* aDst0 = sm + E2_AS + ga_row * AS_ROW + ga_half * 16;
    char* bDst0 = sm + E2_BS + bpl * BS_PL + brow * BS_ROW + bseg * 16;

    const float* rsrc = hn + (size_t)s_src[ga_row] * 128 + ga_half * 8;
    const float* rdst = hn + (size_t)s_dst[ga_row] * 128 + ga_half * 8;
    const float* redg = he + (size_t)(row_base + ga_row) * 128 + ga_half * 8;

#define GATHER_A(c, o0, o1) do { \
        const float* _b; \
        if ((c) < 8)       _b = rsrc; \
        else if ((c) < 16) _b = rdst; \
        else               _b = redg; \
        const int _k = ((c) & 7) * 16; \
        (o0) = *(const float4*)(_b + _k); \
        (o1) = *(const float4*)(_b + _k + 4); \
    } while (0)
#define STORE_A(db, v0, v1) do { \
        uint4 _hi, _lo; \
        split2h((v0).x, (v0).y, _hi.x, _lo.x); \
        split2h((v0).z, (v0).w, _hi.y, _lo.y); \
        split2h((v1).x, (v1).y, _hi.z, _lo.z); \
        split2h((v1).z, (v1).w, _hi.w, _lo.w); \
        char* _d = aDst0 + (db) * AS2_DB; \
        *(uint4*)_d = _hi; \
        *(uint4*)(_d + AS2_PL) = _lo; \
    } while (0)

    {
        float4 a0, a1;
        GATHER_A(0, a0, a1);
        STORE_A(0, a0, a1);
        uint4 v0 = *(const uint4*)gB0;
        uint4 v1 = *(const uint4*)(gB0 + 64);
        *(uint4*)bDst0 = v0;
        *(uint4*)(bDst0 + 128) = v1;
    }
    __syncthreads();

    const uint32_t aB = smb + E2_AS + (warpM * 32 + (lane & 15)) * AS_ROW + (lane >> 4) * 16;
    const uint32_t bB = smb + E2_BS + (((lane >> 3) & 1) * 8 + (lane & 7)) * BS_ROW
                        + (warpN * 64 + (lane >> 4) * 8) * 2;

    for (int c = 0; c < 24; c++) {
        const int db = c & 1;
        float4 a0, a1;
        uint4 w0, w1;
        if (c < 23) {
            GATHER_A(c + 1, a0, a1);
            const unsigned short* g2 = gB0 + (size_t)(c + 1) * 4096;
            w0 = *(const uint4*)g2;
            w1 = *(const uint4*)(g2 + 64);
        }
        mma_chunk128(aB + db * AS2_DB, aB + db * AS2_DB + AS2_PL, 16 * AS_ROW,
                     bB + db * BS_DB, bB + db * BS_DB + BS_PL, acc);
        if (c < 23) {
            STORE_A(db ^ 1, a0, a1);
            char* d = bDst0 + (db ^ 1) * BS_DB;
            *(uint4*)d = w0;
            *(uint4*)(d + 128) = w1;
        }
        __syncthreads();
    }

    // -------- epilogue 1: bias+relu -> split -> Hsm --------------------------
#pragma unroll
    for (int mf = 0; mf < 2; mf++) {
        const int R0 = warpM * 32 + mf * 16 + (lane >> 2);
#pragma unroll
        for (int nf = 0; nf < 8; nf++) {
            const int C0 = warpN * 64 + nf * 8 + (lane & 3) * 2;
            const float bx = b1[C0], by = b1[C0 + 1];
            uint32_t hi, lo;
            split2h(fmaxf(acc[mf][nf][0] + bx, 0.f), fmaxf(acc[mf][nf][1] + by, 0.f), hi, lo);
            *(uint32_t*)(sm + E2_HSM + R0 * HSM_ROW + C0 * 2) = hi;
            *(uint32_t*)(sm + E2_HSM + HSM2_PL + R0 * HSM_ROW + C0 * 2) = lo;
            split2h(fmaxf(acc[mf][nf][2] + bx, 0.f), fmaxf(acc[mf][nf][3] + by, 0.f), hi, lo);
            *(uint32_t*)(sm + E2_HSM + (R0 + 8) * HSM_ROW + C0 * 2) = hi;
            *(uint32_t*)(sm + E2_HSM + HSM2_PL + (R0 + 8) * HSM_ROW + C0 * 2) = lo;
        }
    }
    zero_acc16(acc);

    // -------- stage 2 + epilogue 2: out -> h_edges, atomic-add -> m_node -----
    run_stage2_128(sm, smb, w2c, acc, tid, lane, warpM, warpN);

#pragma unroll
    for (int mf = 0; mf < 2; mf++) {
        const int R0 = warpM * 32 + mf * 16 + (lane >> 2);
#pragma unroll
        for (int nf = 0; nf < 8; nf++) {
            const int C0 = warpN * 64 + nf * 8 + (lane & 3) * 2;
            const float bx = b2[C0], by = b2[C0 + 1];
            float* p0 = he + (size_t)(row_base + R0) * 128 + C0;
            float2 r = *(float2*)p0;
            float2 o;
            o.x = acc[mf][nf][0] + bx + r.x;
            o.y = acc[mf][nf][1] + by + r.y;
            *(float2*)p0 = o;
            float* q0 = mnode + (size_t)s_dst[R0] * 128 + C0;
            atomicAdd(q0, o.x);
            atomicAdd(q0 + 1, o.y);
            float* p1 = he + (size_t)(row_base + R0 + 8) * 128 + C0;
            r = *(float2*)p1;
            o.x = acc[mf][nf][2] + bx + r.x;
            o.y = acc[mf][nf][3] + by + r.y;
            *(float2*)p1 = o;
            float* q1 = mnode + (size_t)s_dst[R0 + 8] * 128 + C0;
            atomicAdd(q1, o.x);
            atomicAdd(q1 + 1, o.y);
        }
    }
#undef GATHER_A
#undef STORE_A
}

// ---------------- node update: 4-stage HMMA chain (64-row tile) --------------
__global__ __launch_bounds__(256)
void node_update_mma(float* __restrict__ hn, const float* __restrict__ mn,
                     const unsigned short* __restrict__ w1c,
                     const unsigned short* __restrict__ w2c,
                     const unsigned short* __restrict__ w3c,
                     const unsigned short* __restrict__ w4c,
                     const float* __restrict__ nb1, const float* __restrict__ nb2,
                     const float* __restrict__ fb1, const float* __restrict__ fb2) {
    extern __shared__ char sm[];
    const uint32_t smb = smem_u32(sm);
    const int tid = threadIdx.x, lane = tid & 31, wid = tid >> 5;
    const int warpM = wid & 1, warpN = wid >> 1;
    const int row_base = blockIdx.x * 64;

    float acc[2][4][4];
    zero_acc8(acc);

    const int ga_row = tid >> 2, ga_q = tid & 3;
    const int grow = min(row_base + ga_row, Nn - 1);
    const float* rn = hn + (size_t)grow * 128;
    const float* rm = mn + (size_t)grow * 128;
    const int bpl = tid >> 7, brow = (tid >> 3) & 15, bseg = tid & 7;
    const unsigned short* gB0 = w1c + bpl * 2048 + brow * 128 + bseg * 8;
    char* aDst0 = sm + EU_AS + ga_row * AS_ROW + ga_q * 8;
    char* bDst0 = sm + EU_BS + bpl * BS_PL + brow * BS_ROW + bseg * 16;

#define NGATHER(c, out) do { \
        const float* _b = ((c) < 8) ? rn : rm; \
        (out) = *(const float4*)(_b + ((c) & 7) * 16 + ga_q * 4); \
    } while (0)
#define NSTORE(db, v) do { \
        uint32_t _h0, _l0, _h1, _l1; \
        split2h((v).x, (v).y, _h0, _l0); \
        split2h((v).z, (v).w, _h1, _l1); \
        char* _d = aDst0 + (db) * AS_DB; \
        *(uint2*)_d = make_uint2(_h0, _h1); \
        *(uint2*)(_d + AS_PL) = make_uint2(_l0, _l1); \
    } while (0)

    {
        float4 a0;
        NGATHER(0, a0);
        NSTORE(0, a0);
        uint4 v0 = *(const uint4*)gB0;
        uint4 v1 = *(const uint4*)(gB0 + 64);
        *(uint4*)bDst0 = v0;
        *(uint4*)(bDst0 + 128) = v1;
    }
    __syncthreads();

    const uint32_t aB = smb + EU_AS + (warpM * 32 + (lane & 15)) * AS_ROW + (lane >> 4) * 16;
    const uint32_t bB = smb + EU_BS + (((lane >> 3) & 1) * 8 + (lane & 7)) * BS_ROW
                        + (warpN * 32 + (lane >> 4) * 8) * 2;

    for (int c = 0; c < 16; c++) {
        const int db = c & 1;
        float4 av;
        uint4 w0, w1;
        if (c < 15) {
            NGATHER(c + 1, av);
            const unsigned short* g2 = gB0 + (size_t)(c + 1) * 4096;
            w0 = *(const uint4*)g2;
            w1 = *(const uint4*)(g2 + 64);
        }
        mma_chunk(aB + db * AS_DB, aB + db * AS_DB + AS_PL, 16 * AS_ROW,
                  bB + db * BS_DB, bB + db * BS_DB + BS_PL, acc);
        if (c < 15) {
            NSTORE(db ^ 1, av);
            char* d = bDst0 + (db ^ 1) * BS_DB;
            *(uint4*)d = w0;
            *(uint4*)(d + 128) = w1;
        }
        __syncthreads();
    }

    // E1: bias+relu -> split -> Hsm
#pragma unroll
    for (int mf = 0; mf < 2; mf++) {
        const int R0 = warpM * 32 + mf * 16 + (lane >> 2);
#pragma unroll
        for (int nf = 0; nf < 4; nf++) {
            const int C0 = warpN * 32 + nf * 8 + (lane & 3) * 2;
            const float bx = nb1[C0], by = nb1[C0 + 1];
            uint32_t hi, lo;
            split2h(fmaxf(acc[mf][nf][0] + bx, 0.f), fmaxf(acc[mf][nf][1] + by, 0.f), hi, lo);
            *(uint32_t*)(sm + EU_HSM + R0 * HSM_ROW + C0 * 2) = hi;
            *(uint32_t*)(sm + EU_HSM + HSM_PL + R0 * HSM_ROW + C0 * 2) = lo;
            split2h(fmaxf(acc[mf][nf][2] + bx, 0.f), fmaxf(acc[mf][nf][3] + by, 0.f), hi, lo);
            *(uint32_t*)(sm + EU_HSM + (R0 + 8) * HSM_ROW + C0 * 2) = hi;
            *(uint32_t*)(sm + EU_HSM + HSM_PL + (R0 + 8) * HSM_ROW + C0 * 2) = lo;
        }
    }
    zero_acc8(acc);

    // stage 2: local = hidden @ nuW2 + b2 + h_nodes
    run_stage2(sm, smb, EU_HSM, EU_BS, w2c, acc, tid, lane, warpM, warpN);
#pragma unroll
    for (int mf = 0; mf < 2; mf++) {
        const int R0 = warpM * 32 + mf * 16 + (lane >> 2);
#pragma unroll
        for (int nf = 0; nf < 4; nf++) {
            const int C0 = warpN * 32 + nf * 8 + (lane & 3) * 2;
            const float bx = nb2[C0], by = nb2[C0 + 1];
            const int g0 = min(row_base + R0, Nn - 1);
            float2 r = *(const float2*)(hn + (size_t)g0 * 128 + C0);
            uint32_t hi, lo;
            split2h(acc[mf][nf][0] + bx + r.x, acc[mf][nf][1] + by + r.y, hi, lo);
            *(uint32_t*)(sm + EU_HSM + R0 * HSM_ROW + C0 * 2) = hi;
            *(uint32_t*)(sm + EU_HSM + HSM_PL + R0 * HSM_ROW + C0 * 2) = lo;
            const int g1 = min(row_base + R0 + 8, Nn - 1);
            r = *(const float2*)(hn + (size_t)g1 * 128 + C0);
            split2h(acc[mf][nf][2] + bx + r.x, acc[mf][nf][3] + by + r.y, hi, lo);
            *(uint32_t*)(sm + EU_HSM + (R0 + 8) * HSM_ROW + C0 * 2) = hi;
            *(uint32_t*)(sm + EU_HSM + HSM_PL + (R0 + 8) * HSM_ROW + C0 * 2) = lo;
        }
    }
    zero_acc8(acc);
    __syncthreads();

    // stage 3: t1 = relu(local @ fuW1 + b1)
    run_stage2(sm, smb, EU_HSM, EU_BS, w3c, acc, tid, lane, warpM, warpN);
#pragma unroll
    for (int mf = 0; mf < 2; mf++) {
        const int R0 = warpM * 32 + mf * 16 + (lane >> 2);
#pragma unroll
        for (int nf = 0; nf < 4; nf++) {
            const int C0 = warpN * 32 + nf * 8 + (lane & 3) * 2;
            const float bx = fb1[C0], by = fb1[C0 + 1];
            uint32_t hi, lo;
            split2h(fmaxf(acc[mf][nf][0] + bx, 0.f), fmaxf(acc[mf][nf][1] + by, 0.f), hi, lo);
            *(uint32_t*)(sm + EU_HSM + R0 * HSM_ROW + C0 * 2) = hi;
            *(uint32_t*)(sm + EU_HSM + HSM_PL + R0 * HSM_ROW + C0 * 2) = lo;
            split2h(fmaxf(acc[mf][nf][2] + bx, 0.f), fmaxf(acc[mf][nf][3] + by, 0.f), hi, lo);
            *(uint32_t*)(sm + EU_HSM + (R0 + 8) * HSM_ROW + C0 * 2) = hi;
            *(uint32_t*)(sm + EU_HSM + HSM_PL + (R0 + 8) * HSM_ROW + C0 * 2) = lo;
        }
    }
    zero_acc8(acc);
    __syncthreads();

    // stage 4: h_nodes = t1 @ fuW2 + b2
    run_stage2(sm, smb, EU_HSM, EU_BS, w4c, acc, tid, lane, warpM, warpN);
#pragma unroll
    for (int mf = 0; mf < 2; mf++) {
        const int R0 = warpM * 32 + mf * 16 + (lane >> 2);
#pragma unroll
        for (int nf = 0; nf < 4; nf++) {
            const int C0 = warpN * 32 + nf * 8 + (lane & 3) * 2;
            const float bx = fb2[C0], by = fb2[C0 + 1];
            const int g0 = row_base + R0;
            if (g0 < Nn) {
                float2 o;
                o.x = acc[mf][nf][0] + bx;
                o.y = acc[mf][nf][1] + by;
                *(float2*)(hn + (size_t)g0 * 128 + C0) = o;
            }
            const int g1 = row_base + R0 + 8;
            if (g1 < Nn) {
                float2 o;
                o.x = acc[mf][nf][2] + bx;
                o.y = acc[mf][nf][3] + by;
                *(float2*)(hn + (size_t)g1 * 128 + C0) = o;
            }
        }
    }
#undef NGATHER
#undef NSTORE
}

// ---------------- edge encoder: fp32 L1 + HMMA L2 (64-row tile) --------------
__global__ __launch_bounds__(256)
void edge_encode_mma(const float* __restrict__ ea,
                     const float* __restrict__ W1, const float* __restrict__ b1,
                     const unsigned short* __restrict__ w2c,
                     const float* __restrict__ b2, float* __restrict__ he) {
    extern __shared__ char sm[];
    const uint32_t smb = smem_u32(sm);
    const int tid = threadIdx.x, lane = tid & 31, wid = tid >> 5;
    const int warpM = wid & 1, warpN = wid >> 1;
    const int row_base = blockIdx.x * 64;
    float* sw1 = (float*)(sm + EE_W1);
    float* sb1 = (float*)(sm + EE_B1);
    sw1[tid] = W1[tid];
    sw1[tid + 256] = W1[tid + 256];
    if (tid < 128) sb1[tid] = b1[tid];
    __syncthreads();

    const int row = tid >> 2, q = tid & 3;
    const float4 e = *(const float4*)(ea + (size_t)(row_base + row) * 4);
#pragma unroll
    for (int cc = 0; cc < 32; cc += 2) {
        const int c = q * 32 + cc;
        float a0 = sb1[c]     + e.x * sw1[c]       + e.y * sw1[128 + c]
                              + e.z * sw1[256 + c] + e.w * sw1[384 + c];
        float a1 = sb1[c + 1] + e.x * sw1[c + 1]   + e.y * sw1[129 + c]
                              + e.z * sw1[257 + c] + e.w * sw1[385 + c];
        uint32_t hi, lo;
        split2h(fmaxf(a0, 0.f), fmaxf(a1, 0.f), hi, lo);
        *(uint32_t*)(sm + EE_HSM + row * HSM_ROW + c * 2) = hi;
        *(uint32_t*)(sm + EE_HSM + HSM_PL + row * HSM_ROW + c * 2) = lo;
    }

    float acc[2][4][4];
    zero_acc8(acc);
    run_stage2(sm, smb, EE_HSM, EE_BS, w2c, acc, tid, lane, warpM, warpN);

#pragma unroll
    for (int mf = 0; mf < 2; mf++) {
        const int R0 = warpM * 32 + mf * 16 + (lane >> 2);
#pragma unroll
        for (int nf = 0; nf < 4; nf++) {
            const int C0 = warpN * 32 + nf * 8 + (lane & 3) * 2;
            const float bx = b2[C0], by = b2[C0 + 1];
            float2 o;
            o.x = acc[mf][nf][0] + bx;
            o.y = acc[mf][nf][1] + by;
            *(float2*)(he + (size_t)(row_base + R0) * 128 + C0) = o;
            o.x = acc[mf][nf][2] + bx;
            o.y = acc[mf][nf][3] + by;
            *(float2*)(he + (size_t)(row_base + R0 + 8) * 128 + C0) = o;
        }
    }
}

// ---------------- small fp32 kernels -----------------------------------------
__global__ void node_encode_kernel(const float* __restrict__ x, const float* __restrict__ pe,
                                   const float* __restrict__ W1, const float* __restrict__ b1,
                                   const float* __restrict__ W2, const float* __restrict__ b2,
                                   const int* __restrict__ node_types,
                                   float* __restrict__ h_nodes) {
    const int node = blockIdx.x;
    const int j = threadIdx.x;
    __shared__ float z[16];
    __shared__ float h[128];
    if (j < IND) z[j] = x[(size_t)node * IND + j];
    else if (j < IND + PED) z[j] = pe[(size_t)node * PED + (j - IND)];
    const int ty = node_types[node];
    __syncthreads();
    const float* w1 = W1 + (size_t)ty * (IND + PED) * Hh;
    float acc = b1[ty * Hh + j];
#pragma unroll
    for (int i = 0; i < IND + PED; i++) acc = fmaf(z[i], w1[i * Hh + j], acc);
    h[j] = fmaxf(acc, 0.f);
    __syncthreads();
    const float* w2 = W2 + (size_t)ty * Hh * Hh;
    float acc2 = b2[ty * Hh + j];
#pragma unroll 8
    for (int k = 0; k < Hh; k++) acc2 = fmaf(h[k], w2[k * Hh + j], acc2);
    h_nodes[(size_t)node * Hh + j] = acc2;
}

__global__ void zero_kernel(float* __restrict__ p, int n) {
    const int i = blockIdx.x * blockDim.x + threadIdx.x;
    if (i < n) p[i] = 0.f;
}

__global__ void decode_kernel(const float* __restrict__ h_nodes,
                              const float* __restrict__ W1, const float* __restrict__ b1,
                              const float* __restrict__ W2, const float* __restrict__ b2,
                              const int* __restrict__ node_types,
                              float* __restrict__ out) {
    const int node = blockIdx.x;
    const int t = threadIdx.x;
    __shared__ float hin[128];
    __shared__ float h[128];
    hin[t] = h_nodes[(size_t)node * Hh + t];
    const int ty = node_types[node];
    __syncthreads();
    const float* w1 = W1 + (size_t)ty * Hh * Hh;
    float acc = b1[ty * Hh + t];
#pragma unroll 8
    for (int k = 0; k < Hh; k++) acc = fmaf(hin[k], w1[k * Hh + t], acc);
    h[t] = fmaxf(acc, 0.f);
    __syncthreads();
    const int o = t >> 5, lane = t & 31;
    const float* w2 = W2 + (size_t)ty * Hh * OUTD;
    float s = 0.f;
#pragma unroll
    for (int k = lane; k < Hh; k += 32) s = fmaf(h[k], w2[k * OUTD + o], s);
#pragma unroll
    for (int off = 16; off; off >>= 1) s += __shfl_down_sync(0xffffffffu, s, off);
    if (lane == 0) out[(size_t)node * OUTD + o] = s + b2[ty * OUTD + o];
}

// ---------------- launch ------------------------------------------------------
extern "C" void kernel_launch(void* const* d_in, const int* in_sizes, int n_in,
                              void* d_out, int out_size) {
    const float* x        = (const float*)d_in[0];
    const float* pe       = (const float*)d_in[1];
    const float* edge_attr= (const float*)d_in[2];
    const float* enc_W1   = (const float*)d_in[3];
    const float* enc_b1   = (const float*)d_in[4];
    const float* enc_W2   = (const float*)d_in[5];
    const float* enc_b2   = (const float*)d_in[6];
    const float* ee_W1    = (const float*)d_in[7];
    const float* ee_b1    = (const float*)d_in[8];
    const float* ee_W2    = (const float*)d_in[9];
    const float* ee_b2    = (const float*)d_in[10];
    const float* eu_W1    = (const float*)d_in[11];
    const float* eu_b1    = (const float*)d_in[12];
    const float* eu_W2    = (const float*)d_in[13];
    const float* eu_b2    = (const float*)d_in[14];
    const float* nu_W1    = (const float*)d_in[15];
    const float* nu_b1    = (const float*)d_in[16];
    const float* nu_W2    = (const float*)d_in[17];
    const float* nu_b2    = (const float*)d_in[18];
    const float* fu_W1    = (const float*)d_in[19];
    const float* fu_b1    = (const float*)d_in[20];
    const float* fu_W2    = (const float*)d_in[21];
    const float* fu_b2    = (const float*)d_in[22];
    const float* dec_W1   = (const float*)d_in[23];
    const float* dec_b1   = (const float*)d_in[24];
    const float* dec_W2   = (const float*)d_in[25];
    const float* dec_b2   = (const float*)d_in[26];
    const int*   edge_index = (const int*)d_in[27];
    const int*   node_types = (const int*)d_in[28];
    float* out = (float*)d_out;

    float *h_nodes, *h_edges, *m_node;
    unsigned short* wc;
    cudaGetSymbolAddress((void**)&h_nodes, g_h_nodes);
    cudaGetSymbolAddress((void**)&h_edges, g_h_edges);
    cudaGetSymbolAddress((void**)&m_node, g_m_node);
    cudaGetSymbolAddress((void**)&wc, g_wc);

    cudaFuncSetAttribute(edge_update_mma, cudaFuncAttributeMaxDynamicSharedMemorySize, E2_SMEM);
    cudaFuncSetAttribute(node_update_mma, cudaFuncAttributeMaxDynamicSharedMemorySize, EU_SMEM);
    cudaFuncSetAttribute(edge_encode_mma, cudaFuncAttributeMaxDynamicSharedMemorySize, EE_SMEM);

    const int* srcp = edge_index;
    const int* dstp = edge_index + Ee;

    prep_weights<<<224, 256>>>(ee_W2, eu_W1, eu_W2, nu_W1, nu_W2, fu_W1, fu_W2);
    node_encode_kernel<<<Nn, 128>>>(x, pe, enc_W1, enc_b1, enc_W2, enc_b2,
                                    node_types, h_nodes);
    edge_encode_mma<<<Ee / 64, 256, EE_SMEM>>>(edge_attr, ee_W1, ee_b1, wc, ee_b2, h_edges);

    for (int l = 0; l < Ll; l++) {
        const unsigned short* w1c = wc + (size_t)(8 + l * 32) * 4096;
        const unsigned short* w2c = w1c + (size_t)24 * 4096;
        const unsigned short* wn  = wc + (size_t)(104 + l * 40) * 4096;
        zero_kernel<<<(Nn * Hh + 255) / 256, 256>>>(m_node, Nn * Hh);
        edge_update_mma<<<Ee / 128, 256, E2_SMEM>>>(
            h_nodes, h_edges, srcp, dstp, w1c, w2c,
            eu_b1 + (size_t)l * Hh, eu_b2 + (size_t)l * Hh, m_node);
        node_update_mma<<<(Nn + 63) / 64, 256, EU_SMEM>>>(
            h_nodes, m_node,
            wn, wn + (size_t)16 * 4096, wn + (size_t)24 * 4096, wn + (size_t)32 * 4096,
            nu_b1 + (size_t)l * Hh, nu_b2 + (size_t)l * Hh,
            fu_b1 + (size_t)l * Hh, fu_b2 + (size_t)l * Hh);
    }

    decode_kernel<<<Nn, 128>>>(h_nodes, dec_W1, dec_b1, dec_W2, dec_b2,
                               node_types, out);
}

// round 15
// speedup vs baseline: 1.1422x; 1.1422x over previous
#include <cuda_runtime.h>
#include <cuda_fp16.h>
#include <stdint.h>

#define Nn   20000
#define Ee   320000
#define Hh   128
#define Ll   3
#define IND  6
#define PED  8
#define OUTD 4

// ---------------- scratch (static device globals; no allocation) -------------
__device__ float g_h_nodes[(size_t)Nn * Hh];
__device__ float g_h_edges[(size_t)Ee * Hh];
__device__ float g_m_node[(size_t)Nn * Hh];
// pre-split fp16 weight chunks: each chunk = [plane(hi,lo)][16 k][128 n] = 4096 halfs.
// 0..7: ee_W2 ; 8+32l..: eu_W1(24), eu_W2(8) ; 104+40l..: nu_W1(16), nu_W2(8), fu_W1(8), fu_W2(8)
__device__ unsigned short g_wc[224 * 4096];

// ---------------- SMEM layout (bytes), shared by edge + node kernels ---------
#define EU_SRC 0
#define EU_DST 256
#define EU_AS  512
#define EU_BS  12800
#define EU_HSM 30208
#define EU_SMEM 65024
// edge_encode layout
#define EE_W1  0
#define EE_B1  2048
#define EE_HSM 2560
#define EE_BS  37376
#define EE_SMEM 54784
// strides
#define AS_DB 6144
#define AS_PL 3072
#define AS_ROW 48
#define BS_DB 8704
#define BS_PL 4352
#define BS_ROW 272
#define HSM_PL 17408
#define HSM_ROW 272

// ---------------- asm wrappers -----------------------------------------------
__device__ __forceinline__ uint32_t smem_u32(const void* p) {
    uint32_t a;
    asm("{ .reg .u64 t; cvta.to.shared.u64 t, %1; cvt.u32.u64 %0, t; }" : "=r"(a) : "l"(p));
    return a;
}
__device__ __forceinline__ void ldsm_x4(uint32_t* r, uint32_t a) {
    asm volatile("ldmatrix.sync.aligned.m8n8.x4.shared.b16 {%0,%1,%2,%3}, [%4];"
                 : "=r"(r[0]), "=r"(r[1]), "=r"(r[2]), "=r"(r[3]) : "r"(a));
}
__device__ __forceinline__ void ldsm_x4t(uint32_t* r, uint32_t a) {
    asm volatile("ldmatrix.sync.aligned.m8n8.x4.trans.shared.b16 {%0,%1,%2,%3}, [%4];"
                 : "=r"(r[0]), "=r"(r[1]), "=r"(r[2]), "=r"(r[3]) : "r"(a));
}
__device__ __forceinline__ void mma16816(float* c, const uint32_t* a, const uint32_t* b) {
    asm volatile("mma.sync.aligned.m16n8k16.row.col.f32.f16.f16.f32 "
                 "{%0,%1,%2,%3}, {%4,%5,%6,%7}, {%8,%9}, {%0,%1,%2,%3};"
                 : "+f"(c[0]), "+f"(c[1]), "+f"(c[2]), "+f"(c[3])
                 : "r"(a[0]), "r"(a[1]), "r"(a[2]), "r"(a[3]), "r"(b[0]), "r"(b[1]));
}
__device__ __forceinline__ uint32_t packh2(__half a, __half b) {
    __half2 h = __halves2half2(a, b);
    return *reinterpret_cast<uint32_t*>(&h);
}
__device__ __forceinline__ void split2h(float x, float y, uint32_t& hi, uint32_t& lo) {
    __half hx = __float2half_rn(x), hy = __float2half_rn(y);
    lo = packh2(__float2half_rn(x - __half2float(hx)),
                __float2half_rn(y - __half2float(hy)));
    hi = packh2(hx, hy);
}
__device__ __forceinline__ void zero_acc8(float acc[2][4][4]) {
#pragma unroll
    for (int i = 0; i < 2; i++)
#pragma unroll
        for (int j = 0; j < 4; j++)
#pragma unroll
            for (int k = 0; k < 4; k++) acc[i][j][k] = 0.f;
}

// one K=16 chunk: 3-term split mma over warp tile 32x32
__device__ __forceinline__ void mma_chunk(uint32_t aHi, uint32_t aLo, uint32_t mfs,
                                          uint32_t bHi, uint32_t bLo,
                                          float acc[2][4][4]) {
    uint32_t ah[2][4], al[2][4], bh[8], bl[8];
    ldsm_x4(ah[0], aHi);
    ldsm_x4(ah[1], aHi + mfs);
    ldsm_x4(al[0], aLo);
    ldsm_x4(al[1], aLo + mfs);
    ldsm_x4t(bh, bHi);
    ldsm_x4t(bh + 4, bHi + 32);
    ldsm_x4t(bl, bLo);
    ldsm_x4t(bl + 4, bLo + 32);
#pragma unroll
    for (int mf = 0; mf < 2; mf++)
#pragma unroll
        for (int nf = 0; nf < 4; nf++) {
            mma16816(acc[mf][nf], ah[mf], bh + 2 * nf);
            mma16816(acc[mf][nf], ah[mf], bl + 2 * nf);
            mma16816(acc[mf][nf], al[mf], bh + 2 * nf);
        }
}

// stage GEMM with A = Hsm (64x128 split fp16), B = 8 streamed weight chunks
__device__ __forceinline__ void run_stage2(char* sm, uint32_t smb,
                                           uint32_t HsmOff, uint32_t BsOff,
                                           const unsigned short* wsrc,
                                           float acc[2][4][4],
                                           int tid, int lane, int warpM, int warpN) {
    const int bpl = tid >> 7, brow = (tid >> 3) & 15, bseg = tid & 7;
    const unsigned short* g0 = wsrc + bpl * 2048 + brow * 128 + bseg * 8;
    char* bdst0 = sm + BsOff + bpl * BS_PL + brow * BS_ROW + bseg * 16;
    {
        uint4 v0 = *(const uint4*)g0;
        uint4 v1 = *(const uint4*)(g0 + 64);
        *(uint4*)bdst0 = v0;
        *(uint4*)(bdst0 + 128) = v1;
    }
    __syncthreads();
    const uint32_t aB = smb + HsmOff + (warpM * 32 + (lane & 15)) * HSM_ROW + (lane >> 4) * 16;
    const uint32_t bB = smb + BsOff + (((lane >> 3) & 1) * 8 + (lane & 7)) * BS_ROW
                        + (warpN * 32 + (lane >> 4) * 8) * 2;
    for (int c = 0; c < 8; c++) {
        const int db = c & 1;
        uint4 w0, w1;
        if (c < 7) {
            const unsigned short* g2 = g0 + (size_t)(c + 1) * 4096;
            w0 = *(const uint4*)g2;
            w1 = *(const uint4*)(g2 + 64);
        }
        mma_chunk(aB + c * 32, aB + c * 32 + HSM_PL, 16 * HSM_ROW,
                  bB + db * BS_DB, bB + db * BS_DB + BS_PL, acc);
        if (c < 7) {
            char* d = bdst0 + (db ^ 1) * BS_DB;
            *(uint4*)d = w0;
            *(uint4*)(d + 128) = w1;
        }
        __syncthreads();
    }
}

// ---------------- weight prep: split fp16 chunks into g_wc -------------------
__global__ void prep_weights(const float* __restrict__ ee_W2,
                             const float* __restrict__ eu_W1,
                             const float* __restrict__ eu_W2,
                             const float* __restrict__ nu_W1,
                             const float* __restrict__ nu_W2,
                             const float* __restrict__ fu_W1,
                             const float* __restrict__ fu_W2) {
    const int cid = blockIdx.x;  // 0..223
    const float* W;
    int koff;
    if (cid < 8) { W = ee_W2; koff = cid * 16; }
    else if (cid < 104) {
        int rel = cid - 8, l = rel / 32, c = rel % 32;
        if (c < 24) { W = eu_W1 + (size_t)l * 3 * Hh * Hh; koff = c * 16; }
        else        { W = eu_W2 + (size_t)l * Hh * Hh;     koff = (c - 24) * 16; }
    } else {
        int rel = cid - 104, l = rel / 40, c = rel % 40;
        if (c < 16)      { W = nu_W1 + (size_t)l * 2 * Hh * Hh; koff = c * 16; }
        else if (c < 24) { W = nu_W2 + (size_t)l * Hh * Hh;     koff = (c - 16) * 16; }
        else if (c < 32) { W = fu_W1 + (size_t)l * Hh * Hh;     koff = (c - 24) * 16; }
        else             { W = fu_W2 + (size_t)l * Hh * Hh;     koff = (c - 32) * 16; }
    }
    unsigned short* out = g_wc + (size_t)cid * 4096;
    for (int idx = threadIdx.x; idx < 2048; idx += blockDim.x) {
        int k = idx >> 7, n = idx & 127;
        float v = W[(size_t)(koff + k) * 128 + n];
        __half h = __float2half_rn(v);
        __half lo = __float2half_rn(v - __half2float(h));
        out[idx] = *reinterpret_cast<unsigned short*>(&h);
        out[2048 + idx] = *reinterpret_cast<unsigned short*>(&lo);
    }
}

// ---------------- edge update: HMMA + fused scatter-add ----------------------
__global__ __launch_bounds__(256, 3)
void edge_update_mma(const float* __restrict__ hn, float* __restrict__ he,
                     const int* __restrict__ src, const int* __restrict__ dst,
                     const unsigned short* __restrict__ w1c,
                     const unsigned short* __restrict__ w2c,
                     const float* __restrict__ b1, const float* __restrict__ b2,
                     float* __restrict__ mnode) {
    extern __shared__ char sm[];
    const uint32_t smb = smem_u32(sm);
    const int tid = threadIdx.x, lane = tid & 31, wid = tid >> 5;
    const int warpM = wid & 1, warpN = wid >> 1;
    const int row_base = blockIdx.x * 64;
    int* s_src = (int*)(sm + EU_SRC);
    int* s_dst = (int*)(sm + EU_DST);
    if (tid < 64) s_src[tid] = src[row_base + tid];
    else if (tid < 128) s_dst[tid - 64] = dst[row_base + tid - 64];
    __syncthreads();

    float acc[2][4][4];
    zero_acc8(acc);

    // -------- stage 1: hidden = relu([h_src||h_dst||h_edge] @ W1 + b1) -------
    const int ga_row = tid >> 2, ga_q = tid & 3;
    const int bpl = tid >> 7, brow = (tid >> 3) & 15, bseg = tid & 7;
    const unsigned short* gB0 = w1c + bpl * 2048 + brow * 128 + bseg * 8;
    char* aDst0 = sm + EU_AS + ga_row * AS_ROW + ga_q * 8;
    char* bDst0 = sm + EU_BS + bpl * BS_PL + brow * BS_ROW + bseg * 16;

    const float* rsrc = hn + (size_t)s_src[ga_row] * 128;
    const float* rdst = hn + (size_t)s_dst[ga_row] * 128;
    const float* redg = he + (size_t)(row_base + ga_row) * 128;

#define GATHER_A(c, out) do { \
        const float* _b; int _k; \
        if ((c) < 8)       { _b = rsrc; _k = (c) * 16; } \
        else if ((c) < 16) { _b = rdst; _k = ((c) - 8) * 16; } \
        else               { _b = redg; _k = ((c) - 16) * 16; } \
        (out) = *(const float4*)(_b + _k + ga_q * 4); \
    } while (0)
#define STORE_A(db, v) do { \
        uint32_t _h0, _l0, _h1, _l1; \
        split2h((v).x, (v).y, _h0, _l0); \
        split2h((v).z, (v).w, _h1, _l1); \
        char* _d = aDst0 + (db) * AS_DB; \
        *(uint2*)_d = make_uint2(_h0, _h1); \
        *(uint2*)(_d + AS_PL) = make_uint2(_l0, _l1); \
    } while (0)

    {
        float4 a0;
        GATHER_A(0, a0);
        STORE_A(0, a0);
        uint4 v0 = *(const uint4*)gB0;
        uint4 v1 = *(const uint4*)(gB0 + 64);
        *(uint4*)bDst0 = v0;
        *(uint4*)(bDst0 + 128) = v1;
    }
    __syncthreads();

    const uint32_t aB = smb + EU_AS + (warpM * 32 + (lane & 15)) * AS_ROW + (lane >> 4) * 16;
    const uint32_t bB = smb + EU_BS + (((lane >> 3) & 1) * 8 + (lane & 7)) * BS_ROW
                        + (warpN * 32 + (lane >> 4) * 8) * 2;

    for (int c = 0; c < 24; c++) {
        const int db = c & 1;
        float4 av;
        uint4 w0, w1;
        if (c < 23) {
            GATHER_A(c + 1, av);
            const unsigned short* g2 = gB0 + (size_t)(c + 1) * 4096;
            w0 = *(const uint4*)g2;
            w1 = *(const uint4*)(g2 + 64);
        }
        mma_chunk(aB + db * AS_DB, aB + db * AS_DB + AS_PL, 16 * AS_ROW,
                  bB + db * BS_DB, bB + db * BS_DB + BS_PL, acc);
        if (c < 23) {
            STORE_A(db ^ 1, av);
            char* d = bDst0 + (db ^ 1) * BS_DB;
            *(uint4*)d = w0;
            *(uint4*)(d + 128) = w1;
        }
        __syncthreads();
    }

    // -------- epilogue 1: bias+relu -> split -> Hsm --------------------------
#pragma unroll
    for (int mf = 0; mf < 2; mf++) {
        const int R0 = warpM * 32 + mf * 16 + (lane >> 2);
#pragma unroll
        for (int nf = 0; nf < 4; nf++) {
            const int C0 = warpN * 32 + nf * 8 + (lane & 3) * 2;
            const float bx = b1[C0], by = b1[C0 + 1];
            uint32_t hi, lo;
            split2h(fmaxf(acc[mf][nf][0] + bx, 0.f), fmaxf(acc[mf][nf][1] + by, 0.f), hi, lo);
            *(uint32_t*)(sm + EU_HSM + R0 * HSM_ROW + C0 * 2) = hi;
            *(uint32_t*)(sm + EU_HSM + HSM_PL + R0 * HSM_ROW + C0 * 2) = lo;
            split2h(fmaxf(acc[mf][nf][2] + bx, 0.f), fmaxf(acc[mf][nf][3] + by, 0.f), hi, lo);
            *(uint32_t*)(sm + EU_HSM + (R0 + 8) * HSM_ROW + C0 * 2) = hi;
            *(uint32_t*)(sm + EU_HSM + HSM_PL + (R0 + 8) * HSM_ROW + C0 * 2) = lo;
        }
    }
    zero_acc8(acc);

    // -------- stage 2 + epilogue 2: out -> h_edges, atomic-add -> m_node -----
    run_stage2(sm, smb, EU_HSM, EU_BS, w2c, acc, tid, lane, warpM, warpN);

#pragma unroll
    for (int mf = 0; mf < 2; mf++) {
        const int R0 = warpM * 32 + mf * 16 + (lane >> 2);
#pragma unroll
        for (int nf = 0; nf < 4; nf++) {
            const int C0 = warpN * 32 + nf * 8 + (lane & 3) * 2;
            const float bx = b2[C0], by = b2[C0 + 1];
            float* p0 = he + (size_t)(row_base + R0) * 128 + C0;
            float2 r = *(float2*)p0;
            float2 o;
            o.x = acc[mf][nf][0] + bx + r.x;
            o.y = acc[mf][nf][1] + by + r.y;
            *(float2*)p0 = o;
            float* q0 = mnode + (size_t)s_dst[R0] * 128 + C0;
            atomicAdd(q0, o.x);
            atomicAdd(q0 + 1, o.y);
            float* p1 = he + (size_t)(row_base + R0 + 8) * 128 + C0;
            r = *(float2*)p1;
            o.x = acc[mf][nf][2] + bx + r.x;
            o.y = acc[mf][nf][3] + by + r.y;
            *(float2*)p1 = o;
            float* q1 = mnode + (size_t)s_dst[R0 + 8] * 128 + C0;
            atomicAdd(q1, o.x);
            atomicAdd(q1 + 1, o.y);
        }
    }
#undef GATHER_A
#undef STORE_A
}

// ---------------- node update: 4-stage HMMA chain ----------------------------
__global__ __launch_bounds__(256, 3)
void node_update_mma(float* __restrict__ hn, const float* __restrict__ mn,
                     const unsigned short* __restrict__ w1c,
                     const unsigned short* __restrict__ w2c,
                     const unsigned short* __restrict__ w3c,
                     const unsigned short* __restrict__ w4c,
                     const float* __restrict__ nb1, const float* __restrict__ nb2,
                     const float* __restrict__ fb1, const float* __restrict__ fb2) {
    extern __shared__ char sm[];
    const uint32_t smb = smem_u32(sm);
    const int tid = threadIdx.x, lane = tid & 31, wid = tid >> 5;
    const int warpM = wid & 1, warpN = wid >> 1;
    const int row_base = blockIdx.x * 64;

    float acc[2][4][4];
    zero_acc8(acc);

    const int ga_row = tid >> 2, ga_q = tid & 3;
    const int grow = min(row_base + ga_row, Nn - 1);
    const float* rn = hn + (size_t)grow * 128;
    const float* rm = mn + (size_t)grow * 128;
    const int bpl = tid >> 7, brow = (tid >> 3) & 15, bseg = tid & 7;
    const unsigned short* gB0 = w1c + bpl * 2048 + brow * 128 + bseg * 8;
    char* aDst0 = sm + EU_AS + ga_row * AS_ROW + ga_q * 8;
    char* bDst0 = sm + EU_BS + bpl * BS_PL + brow * BS_ROW + bseg * 16;

#define NGATHER(c, out) do { \
        const float* _b = ((c) < 8) ? rn : rm; \
        (out) = *(const float4*)(_b + ((c) & 7) * 16 + ga_q * 4); \
    } while (0)
#define NSTORE(db, v) do { \
        uint32_t _h0, _l0, _h1, _l1; \
        split2h((v).x, (v).y, _h0, _l0); \
        split2h((v).z, (v).w, _h1, _l1); \
        char* _d = aDst0 + (db) * AS_DB; \
        *(uint2*)_d = make_uint2(_h0, _h1); \
        *(uint2*)(_d + AS_PL) = make_uint2(_l0, _l1); \
    } while (0)

    {
        float4 a0;
        NGATHER(0, a0);
        NSTORE(0, a0);
        uint4 v0 = *(const uint4*)gB0;
        uint4 v1 = *(const uint4*)(gB0 + 64);
        *(uint4*)bDst0 = v0;
        *(uint4*)(bDst0 + 128) = v1;
    }
    __syncthreads();

    const uint32_t aB = smb + EU_AS + (warpM * 32 + (lane & 15)) * AS_ROW + (lane >> 4) * 16;
    const uint32_t bB = smb + EU_BS + (((lane >> 3) & 1) * 8 + (lane & 7)) * BS_ROW
                        + (warpN * 32 + (lane >> 4) * 8) * 2;

    for (int c = 0; c < 16; c++) {
        const int db = c & 1;
        float4 av;
        uint4 w0, w1;
        if (c < 15) {
            NGATHER(c + 1, av);
            const unsigned short* g2 = gB0 + (size_t)(c + 1) * 4096;
            w0 = *(const uint4*)g2;
            w1 = *(const uint4*)(g2 + 64);
        }
        mma_chunk(aB + db * AS_DB, aB + db * AS_DB + AS_PL, 16 * AS_ROW,
                  bB + db * BS_DB, bB + db * BS_DB + BS_PL, acc);
        if (c < 15) {
            NSTORE(db ^ 1, av);
            char* d = bDst0 + (db ^ 1) * BS_DB;
            *(uint4*)d = w0;
            *(uint4*)(d + 128) = w1;
        }
        __syncthreads();
    }

    // E1: bias+relu -> split -> Hsm
#pragma unroll
    for (int mf = 0; mf < 2; mf++) {
        const int R0 = warpM * 32 + mf * 16 + (lane >> 2);
#pragma unroll
        for (int nf = 0; nf < 4; nf++) {
            const int C0 = warpN * 32 + nf * 8 + (lane & 3) * 2;
            const float bx = nb1[C0], by = nb1[C0 + 1];
            uint32_t hi, lo;
            split2h(fmaxf(acc[mf][nf][0] + bx, 0.f), fmaxf(acc[mf][nf][1] + by, 0.f), hi, lo);
            *(uint32_t*)(sm + EU_HSM + R0 * HSM_ROW + C0 * 2) = hi;
            *(uint32_t*)(sm + EU_HSM + HSM_PL + R0 * HSM_ROW + C0 * 2) = lo;
            split2h(fmaxf(acc[mf][nf][2] + bx, 0.f), fmaxf(acc[mf][nf][3] + by, 0.f), hi, lo);
            *(uint32_t*)(sm + EU_HSM + (R0 + 8) * HSM_ROW + C0 * 2) = hi;
            *(uint32_t*)(sm + EU_HSM + HSM_PL + (R0 + 8) * HSM_ROW + C0 * 2) = lo;
        }
    }
    zero_acc8(acc);

    // stage 2: local = hidden @ nuW2 + b2 + h_nodes
    run_stage2(sm, smb, EU_HSM, EU_BS, w2c, acc, tid, lane, warpM, warpN);
#pragma unroll
    for (int mf = 0; mf < 2; mf++) {
        const int R0 = warpM * 32 + mf * 16 + (lane >> 2);
#pragma unroll
        for (int nf = 0; nf < 4; nf++) {
            const int C0 = warpN * 32 + nf * 8 + (lane & 3) * 2;
            const float bx = nb2[C0], by = nb2[C0 + 1];
            const int g0 = min(row_base + R0, Nn - 1);
            float2 r = *(const float2*)(hn + (size_t)g0 * 128 + C0);
            uint32_t hi, lo;
            split2h(acc[mf][nf][0] + bx + r.x, acc[mf][nf][1] + by + r.y, hi, lo);
            *(uint32_t*)(sm + EU_HSM + R0 * HSM_ROW + C0 * 2) = hi;
            *(uint32_t*)(sm + EU_HSM + HSM_PL + R0 * HSM_ROW + C0 * 2) = lo;
            const int g1 = min(row_base + R0 + 8, Nn - 1);
            r = *(const float2*)(hn + (size_t)g1 * 128 + C0);
            split2h(acc[mf][nf][2] + bx + r.x, acc[mf][nf][3] + by + r.y, hi, lo);
            *(uint32_t*)(sm + EU_HSM + (R0 + 8) * HSM_ROW + C0 * 2) = hi;
            *(uint32_t*)(sm + EU_HSM + HSM_PL + (R0 + 8) * HSM_ROW + C0 * 2) = lo;
        }
    }
    zero_acc8(acc);
    __syncthreads();

    // stage 3: t1 = relu(local @ fuW1 + b1)
    run_stage2(sm, smb, EU_HSM, EU_BS, w3c, acc, tid, lane, warpM, warpN);
#pragma unroll
    for (int mf = 0; mf < 2; mf++) {
        const int R0 = warpM * 32 + mf * 16 + (lane >> 2);
#pragma unroll
        for (int nf = 0; nf < 4; nf++) {
            const int C0 = warpN * 32 + nf * 8 + (lane & 3) * 2;
            const float bx = fb1[C0], by = fb1[C0 + 1];
            uint32_t hi, lo;
            split2h(fmaxf(acc[mf][nf][0] + bx, 0.f), fmaxf(acc[mf][nf][1] + by, 0.f), hi, lo);
            *(uint32_t*)(sm + EU_HSM + R0 * HSM_ROW + C0 * 2) = hi;
            *(uint32_t*)(sm + EU_HSM + HSM_PL + R0 * HSM_ROW + C0 * 2) = lo;
            split2h(fmaxf(acc[mf][nf][2] + bx, 0.f), fmaxf(acc[mf][nf][3] + by, 0.f), hi, lo);
            *(uint32_t*)(sm + EU_HSM + (R0 + 8) * HSM_ROW + C0 * 2) = hi;
            *(uint32_t*)(sm + EU_HSM + HSM_PL + (R0 + 8) * HSM_ROW + C0 * 2) = lo;
        }
    }
    zero_acc8(acc);
    __syncthreads();

    // stage 4: h_nodes = t1 @ fuW2 + b2
    run_stage2(sm, smb, EU_HSM, EU_BS, w4c, acc, tid, lane, warpM, warpN);
#pragma unroll
    for (int mf = 0; mf < 2; mf++) {
        const int R0 = warpM * 32 + mf * 16 + (lane >> 2);
#pragma unroll
        for (int nf = 0; nf < 4; nf++) {
            const int C0 = warpN * 32 + nf * 8 + (lane & 3) * 2;
            const float bx = fb2[C0], by = fb2[C0 + 1];
            const int g0 = row_base + R0;
            if (g0 < Nn) {
                float2 o;
                o.x = acc[mf][nf][0] + bx;
                o.y = acc[mf][nf][1] + by;
                *(float2*)(hn + (size_t)g0 * 128 + C0) = o;
            }
            const int g1 = row_base + R0 + 8;
            if (g1 < Nn) {
                float2 o;
                o.x = acc[mf][nf][2] + bx;
                o.y = acc[mf][nf][3] + by;
                *(float2*)(hn + (size_t)g1 * 128 + C0) = o;
            }
        }
    }
#undef NGATHER
#undef NSTORE
}

// ---------------- edge encoder: fp32 L1 + HMMA L2 ----------------------------
__global__ __launch_bounds__(256, 3)
void edge_encode_mma(const float* __restrict__ ea,
                     const float* __restrict__ W1, const float* __restrict__ b1,
                     const unsigned short* __restrict__ w2c,
                     const float* __restrict__ b2, float* __restrict__ he) {
    extern __shared__ char sm[];
    const uint32_t smb = smem_u32(sm);
    const int tid = threadIdx.x, lane = tid & 31, wid = tid >> 5;
    const int warpM = wid & 1, warpN = wid >> 1;
    const int row_base = blockIdx.x * 64;
    float* sw1 = (float*)(sm + EE_W1);
    float* sb1 = (float*)(sm + EE_B1);
    sw1[tid] = W1[tid];
    sw1[tid + 256] = W1[tid + 256];
    if (tid < 128) sb1[tid] = b1[tid];
    __syncthreads();

    const int row = tid >> 2, q = tid & 3;
    const float4 e = *(const float4*)(ea + (size_t)(row_base + row) * 4);
#pragma unroll
    for (int cc = 0; cc < 32; cc += 2) {
        const int c = q * 32 + cc;
        float a0 = sb1[c]     + e.x * sw1[c]       + e.y * sw1[128 + c]
                              + e.z * sw1[256 + c] + e.w * sw1[384 + c];
        float a1 = sb1[c + 1] + e.x * sw1[c + 1]   + e.y * sw1[129 + c]
                              + e.z * sw1[257 + c] + e.w * sw1[385 + c];
        uint32_t hi, lo;
        split2h(fmaxf(a0, 0.f), fmaxf(a1, 0.f), hi, lo);
        *(uint32_t*)(sm + EE_HSM + row * HSM_ROW + c * 2) = hi;
        *(uint32_t*)(sm + EE_HSM + HSM_PL + row * HSM_ROW + c * 2) = lo;
    }

    float acc[2][4][4];
    zero_acc8(acc);
    run_stage2(sm, smb, EE_HSM, EE_BS, w2c, acc, tid, lane, warpM, warpN);

#pragma unroll
    for (int mf = 0; mf < 2; mf++) {
        const int R0 = warpM * 32 + mf * 16 + (lane >> 2);
#pragma unroll
        for (int nf = 0; nf < 4; nf++) {
            const int C0 = warpN * 32 + nf * 8 + (lane & 3) * 2;
            const float bx = b2[C0], by = b2[C0 + 1];
            float2 o;
            o.x = acc[mf][nf][0] + bx;
            o.y = acc[mf][nf][1] + by;
            *(float2*)(he + (size_t)(row_base + R0) * 128 + C0) = o;
            o.x = acc[mf][nf][2] + bx;
            o.y = acc[mf][nf][3] + by;
            *(float2*)(he + (size_t)(row_base + R0 + 8) * 128 + C0) = o;
        }
    }
}

// ---------------- small fp32 kernels -----------------------------------------
__global__ void node_encode_kernel(const float* __restrict__ x, const float* __restrict__ pe,
                                   const float* __restrict__ W1, const float* __restrict__ b1,
                                   const float* __restrict__ W2, const float* __restrict__ b2,
                                   const int* __restrict__ node_types,
                                   float* __restrict__ h_nodes) {
    const int node = blockIdx.x;
    const int j = threadIdx.x;
    __shared__ float z[16];
    __shared__ float h[128];
    if (j < IND) z[j] = x[(size_t)node * IND + j];
    else if (j < IND + PED) z[j] = pe[(size_t)node * PED + (j - IND)];
    const int ty = node_types[node];
    __syncthreads();
    const float* w1 = W1 + (size_t)ty * (IND + PED) * Hh;
    float acc = b1[ty * Hh + j];
#pragma unroll
    for (int i = 0; i < IND + PED; i++) acc = fmaf(z[i], w1[i * Hh + j], acc);
    h[j] = fmaxf(acc, 0.f);
    __syncthreads();
    const float* w2 = W2 + (size_t)ty * Hh * Hh;
    float acc2 = b2[ty * Hh + j];
#pragma unroll 8
    for (int k = 0; k < Hh; k++) acc2 = fmaf(h[k], w2[k * Hh + j], acc2);
    h_nodes[(size_t)node * Hh + j] = acc2;
}

__global__ void zero_kernel(float* __restrict__ p, int n) {
    const int i = blockIdx.x * blockDim.x + threadIdx.x;
    if (i < n) p[i] = 0.f;
}

__global__ void decode_kernel(const float* __restrict__ h_nodes,
                              const float* __restrict__ W1, const float* __restrict__ b1,
                              const float* __restrict__ W2, const float* __restrict__ b2,
                              const int* __restrict__ node_types,
                              float* __restrict__ out) {
    const int node = blockIdx.x;
    const int t = threadIdx.x;
    __shared__ float hin[128];
    __shared__ float h[128];
    hin[t] = h_nodes[(size_t)node * Hh + t];
    const int ty = node_types[node];
    __syncthreads();
    const float* w1 = W1 + (size_t)ty * Hh * Hh;
    float acc = b1[ty * Hh + t];
#pragma unroll 8
    for (int k = 0; k < Hh; k++) acc = fmaf(hin[k], w1[k * Hh + t], acc);
    h[t] = fmaxf(acc, 0.f);
    __syncthreads();
    const int o = t >> 5, lane = t & 31;
    const float* w2 = W2 + (size_t)ty * Hh * OUTD;
    float s = 0.f;
#pragma unroll
    for (int k = lane; k < Hh; k += 32) s = fmaf(h[k], w2[k * OUTD + o], s);
#pragma unroll
    for (int off = 16; off; off >>= 1) s += __shfl_down_sync(0xffffffffu, s, off);
    if (lane == 0) out[(size_t)node * OUTD + o] = s + b2[ty * OUTD + o];
}

// ---------------- launch ------------------------------------------------------
extern "C" void kernel_launch(void* const* d_in, const int* in_sizes, int n_in,
                              void* d_out, int out_size) {
    const float* x        = (const float*)d_in[0];
    const float* pe       = (const float*)d_in[1];
    const float* edge_attr= (const float*)d_in[2];
    const float* enc_W1   = (const float*)d_in[3];
    const float* enc_b1   = (const float*)d_in[4];
    const float* enc_W2   = (const float*)d_in[5];
    const float* enc_b2   = (const float*)d_in[6];
    const float* ee_W1    = (const float*)d_in[7];
    const float* ee_b1    = (const float*)d_in[8];
    const float* ee_W2    = (const float*)d_in[9];
    const float* ee_b2    = (const float*)d_in[10];
    const float* eu_W1    = (const float*)d_in[11];
    const float* eu_b1    = (const float*)d_in[12];
    const float* eu_W2    = (const float*)d_in[13];
    const float* eu_b2    = (const float*)d_in[14];
    const float* nu_W1    = (const float*)d_in[15];
    const float* nu_b1    = (const float*)d_in[16];
    const float* nu_W2    = (const float*)d_in[17];
    const float* nu_b2    = (const float*)d_in[18];
    const float* fu_W1    = (const float*)d_in[19];
    const float* fu_b1    = (const float*)d_in[20];
    const float* fu_W2    = (const float*)d_in[21];
    const float* fu_b2    = (const float*)d_in[22];
    const float* dec_W1   = (const float*)d_in[23];
    const float* dec_b1   = (const float*)d_in[24];
    const float* dec_W2   = (const float*)d_in[25];
    const float* dec_b2   = (const float*)d_in[26];
    const int*   edge_index = (const int*)d_in[27];
    const int*   node_types = (const int*)d_in[28];
    float* out = (float*)d_out;

    float *h_nodes, *h_edges, *m_node;
    unsigned short* wc;
    cudaGetSymbolAddress((void**)&h_nodes, g_h_nodes);
    cudaGetSymbolAddress((void**)&h_edges, g_h_edges);
    cudaGetSymbolAddress((void**)&m_node, g_m_node);
    cudaGetSymbolAddress((void**)&wc, g_wc);

    cudaFuncSetAttribute(edge_update_mma, cudaFuncAttributeMaxDynamicSharedMemorySize, EU_SMEM);
    cudaFuncSetAttribute(node_update_mma, cudaFuncAttributeMaxDynamicSharedMemorySize, EU_SMEM);
    cudaFuncSetAttribute(edge_encode_mma, cudaFuncAttributeMaxDynamicSharedMemorySize, EE_SMEM);

    const int* srcp = edge_index;
    const int* dstp = edge_index + Ee;

    prep_weights<<<224, 256>>>(ee_W2, eu_W1, eu_W2, nu_W1, nu_W2, fu_W1, fu_W2);
    node_encode_kernel<<<Nn, 128>>>(x, pe, enc_W1, enc_b1, enc_W2, enc_b2,
                                    node_types, h_nodes);
    edge_encode_mma<<<Ee / 64, 256, EE_SMEM>>>(edge_attr, ee_W1, ee_b1, wc, ee_b2, h_edges);

    for (int l = 0; l < Ll; l++) {
        const unsigned short* w1c = wc + (size_t)(8 + l * 32) * 4096;
        const unsigned short* w2c = w1c + (size_t)24 * 4096;
        const unsigned short* wn  = wc + (size_t)(104 + l * 40) * 4096;
        zero_kernel<<<(Nn * Hh + 255) / 256, 256>>>(m_node, Nn * Hh);
        edge_update_mma<<<Ee / 64, 256, EU_SMEM>>>(
            h_nodes, h_edges, srcp, dstp, w1c, w2c,
            eu_b1 + (size_t)l * Hh, eu_b2 + (size_t)l * Hh, m_node);
        node_update_mma<<<(Nn + 63) / 64, 256, EU_SMEM>>>(
            h_nodes, m_node,
            wn, wn + (size_t)16 * 4096, wn + (size_t)24 * 4096, wn + (size_t)32 * 4096,
            nu_b1 + (size_t)l * Hh, nu_b2 + (size_t)l * Hh,
            fu_b1 + (size_t)l * Hh, fu_b2 + (size_t)l * Hh);
    }

    decode_kernel<<<Nn, 128>>>(h_nodes, dec_W1, dec_b1, dec_W2, dec_b2,
                               node_types, out);
}